// round 9
// baseline (speedup 1.0000x reference)
#include <cuda_runtime.h>

// Causal FIR: y[r][t] = sum_{k=0}^{15} b[k] * x[r][t-k], zero init per row.
// x: [64, 480000] f32, b: [16] f32, y: [64, 480000] f32.
//
// R5 ncu: L1 still binding (79.5%) — the 5 overlapping halo loads pay full
// wavefront + data-return cost even as L1 hits (5x read amplification).
//
// This version loads every input float exactly once (coalesced LDG.128) and
// builds each lane's 16-float causal halo from neighbor lanes' registers via
// rotated __shfl_sync + select. Each warp owns a chain of 5 consecutive
// 256-float tiles: the next tile's halo is the previous tile's registers,
// and the global halo load + tap loads happen once per chain. Next-tile
// loads are prefetched before computing the current tile to keep DRAM
// latency covered. L1 drops to ~0.06 wf/output; DRAM becomes the binder.

#define T_LEN    480000
#define NTAPS    16
#define BATCH    64
#define TILE     256                       // floats per warp tile (2 sub-panels)
#define N_TILES  (T_LEN / TILE)            // 1875 tiles per row
#define T_PER    5                         // tiles per warp chain
#define N_CHAIN  (N_TILES / T_PER)         // 375 chains per row
#define WARPS_PB 8
#define BLOCK    (WARPS_PB * 32)

__device__ __forceinline__ float4 shfl4(float4 v, int src) {
    float4 r;
    r.x = __shfl_sync(0xffffffffu, v.x, src);
    r.y = __shfl_sync(0xffffffffu, v.y, src);
    r.z = __shfl_sync(0xffffffffu, v.z, src);
    r.w = __shfl_sync(0xffffffffu, v.w, src);
    return r;
}

__global__ __launch_bounds__(BLOCK, 3)
void fir_apply_kernel(const float* __restrict__ x,
                      const float* __restrict__ b,
                      float* __restrict__ y)
{
    const int lane  = threadIdx.x & 31;
    const int warp  = threadIdx.x >> 5;
    const int chain = blockIdx.x * WARPS_PB + warp;
    if (chain >= N_CHAIN) return;            // warp-uniform exit
    const int row = blockIdx.y;

    const float4* __restrict__ x4 = reinterpret_cast<const float4*>(x + (size_t)row * T_LEN);
    float4* __restrict__ y4 = reinterpret_cast<float4*>(y + (size_t)row * T_LEN);

    // ---- taps (amortized over 5 tiles) ----
    float bb[NTAPS];
    {
        const float4* b4 = reinterpret_cast<const float4*>(b);
        float4 q0 = __ldg(b4 + 0), q1 = __ldg(b4 + 1),
               q2 = __ldg(b4 + 2), q3 = __ldg(b4 + 3);
        bb[0]  = q0.x; bb[1]  = q0.y; bb[2]  = q0.z; bb[3]  = q0.w;
        bb[4]  = q1.x; bb[5]  = q1.y; bb[6]  = q1.z; bb[7]  = q1.w;
        bb[8]  = q2.x; bb[9]  = q2.y; bb[10] = q2.z; bb[11] = q2.w;
        bb[12] = q3.x; bb[13] = q3.y; bb[14] = q3.z; bb[15] = q3.w;
    }

    int pb4 = chain * T_PER * (TILE / 4);    // float4 index of tile base

    // ---- halo for the first tile of the chain: lanes 28..31 hold
    // x[pb-16+4h .. pb-13+4h], h = lane-28. Chain 0 starts at t=0 -> zeros.
    float4 hv = make_float4(0.f, 0.f, 0.f, 0.f);
    if (chain > 0 && lane >= 28)
        hv = __ldg(x4 + (pb4 - 4 + (lane - 28)));

    // ---- preload first tile (coalesced: lane stride 16B) ----
    float4 v0 = __ldg(x4 + pb4 + lane);          // sub-panel 0
    float4 v1 = __ldg(x4 + pb4 + 32 + lane);     // sub-panel 1

    #pragma unroll 1
    for (int t = 0; t < T_PER; t++) {
        // prefetch next tile before computing (overlap DRAM latency)
        float4 nv0, nv1;
        if (t < T_PER - 1) {
            nv0 = __ldg(x4 + pb4 + 64 + lane);
            nv1 = __ldg(x4 + pb4 + 96 + lane);
        }

        // ---- assemble 20-float windows for both sub-panels via shfl ----
        // w[m] = x[t0 - 16 + m]; chain position (lane - d) via rotation.
        float w0[20], w1[20];
        #pragma unroll
        for (int d = 1; d <= 4; d++) {
            const int src = (lane - d) & 31;
            float4 r0 = shfl4(v0, src);          // v0 of lane-d  (wraps)
            float4 r1 = shfl4(v1, src);          // v1 of lane-d  (wraps)
            float4 hh = shfl4(hv, src);          // halo (lanes 28..31 valid)
            // sub-panel 0: lanes < d take halo; sub-panel 1: lanes < d take v0 wrap
            float4 W0, W1;
            W0.x = (lane >= d) ? r0.x : hh.x;  W1.x = (lane >= d) ? r1.x : r0.x;
            W0.y = (lane >= d) ? r0.y : hh.y;  W1.y = (lane >= d) ? r1.y : r0.y;
            W0.z = (lane >= d) ? r0.z : hh.z;  W1.z = (lane >= d) ? r1.z : r0.z;
            W0.w = (lane >= d) ? r0.w : hh.w;  W1.w = (lane >= d) ? r1.w : r0.w;
            const int m = 16 - 4 * d;
            w0[m+0] = W0.x; w0[m+1] = W0.y; w0[m+2] = W0.z; w0[m+3] = W0.w;
            w1[m+0] = W1.x; w1[m+1] = W1.y; w1[m+2] = W1.z; w1[m+3] = W1.w;
        }
        w0[16] = v0.x; w0[17] = v0.y; w0[18] = v0.z; w0[19] = v0.w;
        w1[16] = v1.x; w1[17] = v1.y; w1[18] = v1.z; w1[19] = v1.w;

        // ---- 8 independent FMA chains ----
        float a0 = 0.f, a1 = 0.f, a2 = 0.f, a3 = 0.f;
        float c0 = 0.f, c1 = 0.f, c2 = 0.f, c3 = 0.f;
        #pragma unroll
        for (int k = 0; k < NTAPS; k++) {
            a0 = fmaf(bb[k], w0[16 - k], a0);
            a1 = fmaf(bb[k], w0[17 - k], a1);
            a2 = fmaf(bb[k], w0[18 - k], a2);
            a3 = fmaf(bb[k], w0[19 - k], a3);
            c0 = fmaf(bb[k], w1[16 - k], c0);
            c1 = fmaf(bb[k], w1[17 - k], c1);
            c2 = fmaf(bb[k], w1[18 - k], c2);
            c3 = fmaf(bb[k], w1[19 - k], c3);
        }

        // ---- coalesced stores ----
        y4[pb4 + lane]      = make_float4(a0, a1, a2, a3);
        y4[pb4 + 32 + lane] = make_float4(c0, c1, c2, c3);

        // ---- slide the chain: next tile's halo = this tile's v1 ----
        hv = v1;
        v0 = nv0;
        v1 = nv1;
        pb4 += 64;
    }
}

extern "C" void kernel_launch(void* const* d_in, const int* in_sizes, int n_in,
                              void* d_out, int out_size)
{
    const float* x = (const float*)d_in[0];   // [64, 480000] f32
    const float* b = (const float*)d_in[1];   // [16] f32
    float* y = (float*)d_out;                 // [64, 480000] f32

    dim3 grid((N_CHAIN + WARPS_PB - 1) / WARPS_PB, BATCH, 1);   // (47, 64)
    fir_apply_kernel<<<grid, BLOCK>>>(x, b, y);
}

// round 12
// speedup vs baseline: 1.3320x; 1.3320x over previous
#include <cuda_runtime.h>

// Causal FIR: y[r][t] = sum_{k=0}^{15} b[k] * x[r][t-k], zero init per row.
// x: [64, 480000] f32, b: [16] f32, y: [64, 480000] f32.
//
// R6 ncu: L1 binding (79.5%) — the 5 overlapping halo loads pay full
// wavefront + data-return cost even as L1 hits (5x read amplification).
//
// This version loads every input float exactly once (coalesced LDG.128) and
// builds each lane's 16-float causal halo from neighbor lanes' registers via
// rotated __shfl_sync + select. Each warp owns a chain of 5 consecutive
// 256-float tiles: the next tile's halo is the previous tile's registers,
// and the global halo load + tap loads happen once per chain. Next-tile
// loads are prefetched before computing the current tile to keep DRAM
// latency covered. L1 drops to ~0.06 wf/output; DRAM becomes the binder.

#define T_LEN    480000
#define NTAPS    16
#define BATCH    64
#define TILE     256                       // floats per warp tile (2 sub-panels)
#define N_TILES  (T_LEN / TILE)            // 1875 tiles per row
#define T_PER    5                         // tiles per warp chain
#define N_CHAIN  (N_TILES / T_PER)         // 375 chains per row
#define WARPS_PB 8
#define BLOCK    (WARPS_PB * 32)

__device__ __forceinline__ float4 shfl4(float4 v, int src) {
    float4 r;
    r.x = __shfl_sync(0xffffffffu, v.x, src);
    r.y = __shfl_sync(0xffffffffu, v.y, src);
    r.z = __shfl_sync(0xffffffffu, v.z, src);
    r.w = __shfl_sync(0xffffffffu, v.w, src);
    return r;
}

__global__ __launch_bounds__(BLOCK, 3)
void fir_apply_kernel(const float* __restrict__ x,
                      const float* __restrict__ b,
                      float* __restrict__ y)
{
    const int lane  = threadIdx.x & 31;
    const int warp  = threadIdx.x >> 5;
    const int chain = blockIdx.x * WARPS_PB + warp;
    if (chain >= N_CHAIN) return;            // warp-uniform exit
    const int row = blockIdx.y;

    const float4* __restrict__ x4 = reinterpret_cast<const float4*>(x + (size_t)row * T_LEN);
    float4* __restrict__ y4 = reinterpret_cast<float4*>(y + (size_t)row * T_LEN);

    // ---- taps (amortized over 5 tiles) ----
    float bb[NTAPS];
    {
        const float4* b4 = reinterpret_cast<const float4*>(b);
        float4 q0 = __ldg(b4 + 0), q1 = __ldg(b4 + 1),
               q2 = __ldg(b4 + 2), q3 = __ldg(b4 + 3);
        bb[0]  = q0.x; bb[1]  = q0.y; bb[2]  = q0.z; bb[3]  = q0.w;
        bb[4]  = q1.x; bb[5]  = q1.y; bb[6]  = q1.z; bb[7]  = q1.w;
        bb[8]  = q2.x; bb[9]  = q2.y; bb[10] = q2.z; bb[11] = q2.w;
        bb[12] = q3.x; bb[13] = q3.y; bb[14] = q3.z; bb[15] = q3.w;
    }

    int pb4 = chain * T_PER * (TILE / 4);    // float4 index of tile base

    // ---- halo for the first tile of the chain: lanes 28..31 hold
    // x[pb-16+4h .. pb-13+4h], h = lane-28. Chain 0 starts at t=0 -> zeros.
    float4 hv = make_float4(0.f, 0.f, 0.f, 0.f);
    if (chain > 0 && lane >= 28)
        hv = __ldg(x4 + (pb4 - 4 + (lane - 28)));

    // ---- preload first tile (coalesced: lane stride 16B) ----
    float4 v0 = __ldg(x4 + pb4 + lane);          // sub-panel 0
    float4 v1 = __ldg(x4 + pb4 + 32 + lane);     // sub-panel 1

    #pragma unroll 1
    for (int t = 0; t < T_PER; t++) {
        // prefetch next tile before computing (overlap DRAM latency)
        float4 nv0 = make_float4(0.f, 0.f, 0.f, 0.f);
        float4 nv1 = make_float4(0.f, 0.f, 0.f, 0.f);
        if (t < T_PER - 1) {
            nv0 = __ldg(x4 + pb4 + 64 + lane);
            nv1 = __ldg(x4 + pb4 + 96 + lane);
        }

        // ---- assemble 20-float windows for both sub-panels via shfl ----
        // w[m] = x[t0 - 16 + m]; source lane (lane - d) via rotation.
        float w0[20], w1[20];
        #pragma unroll
        for (int d = 1; d <= 4; d++) {
            const int src = (lane - d) & 31;
            float4 r0 = shfl4(v0, src);          // v0 of lane-d  (wraps)
            float4 r1 = shfl4(v1, src);          // v1 of lane-d  (wraps)
            float4 hh = shfl4(hv, src);          // halo (lanes 28..31 valid)
            // sub-panel 0: lanes < d take halo; sub-panel 1: lanes < d take v0 wrap
            float4 W0, W1;
            W0.x = (lane >= d) ? r0.x : hh.x;  W1.x = (lane >= d) ? r1.x : r0.x;
            W0.y = (lane >= d) ? r0.y : hh.y;  W1.y = (lane >= d) ? r1.y : r0.y;
            W0.z = (lane >= d) ? r0.z : hh.z;  W1.z = (lane >= d) ? r1.z : r0.z;
            W0.w = (lane >= d) ? r0.w : hh.w;  W1.w = (lane >= d) ? r1.w : r0.w;
            const int m = 16 - 4 * d;
            w0[m+0] = W0.x; w0[m+1] = W0.y; w0[m+2] = W0.z; w0[m+3] = W0.w;
            w1[m+0] = W1.x; w1[m+1] = W1.y; w1[m+2] = W1.z; w1[m+3] = W1.w;
        }
        w0[16] = v0.x; w0[17] = v0.y; w0[18] = v0.z; w0[19] = v0.w;
        w1[16] = v1.x; w1[17] = v1.y; w1[18] = v1.z; w1[19] = v1.w;

        // ---- 8 independent FMA chains ----
        float a0 = 0.f, a1 = 0.f, a2 = 0.f, a3 = 0.f;
        float c0 = 0.f, c1 = 0.f, c2 = 0.f, c3 = 0.f;
        #pragma unroll
        for (int k = 0; k < NTAPS; k++) {
            a0 = fmaf(bb[k], w0[16 - k], a0);
            a1 = fmaf(bb[k], w0[17 - k], a1);
            a2 = fmaf(bb[k], w0[18 - k], a2);
            a3 = fmaf(bb[k], w0[19 - k], a3);
            c0 = fmaf(bb[k], w1[16 - k], c0);
            c1 = fmaf(bb[k], w1[17 - k], c1);
            c2 = fmaf(bb[k], w1[18 - k], c2);
            c3 = fmaf(bb[k], w1[19 - k], c3);
        }

        // ---- coalesced stores ----
        y4[pb4 + lane]      = make_float4(a0, a1, a2, a3);
        y4[pb4 + 32 + lane] = make_float4(c0, c1, c2, c3);

        // ---- slide the chain: next tile's halo = this tile's v1 ----
        hv = v1;
        v0 = nv0;
        v1 = nv1;
        pb4 += 64;
    }
}

extern "C" void kernel_launch(void* const* d_in, const int* in_sizes, int n_in,
                              void* d_out, int out_size)
{
    const float* x = (const float*)d_in[0];   // [64, 480000] f32
    const float* b = (const float*)d_in[1];   // [16] f32
    float* y = (float*)d_out;                 // [64, 480000] f32

    dim3 grid((N_CHAIN + WARPS_PB - 1) / WARPS_PB, BATCH, 1);   // (47, 64)
    fir_apply_kernel<<<grid, BLOCK>>>(x, b, y);
}

// round 14
// speedup vs baseline: 1.3833x; 1.0385x over previous
#include <cuda_runtime.h>

// Causal FIR: y[r][t] = sum_{k=0}^{15} b[k] * x[r][t-k], zero init per row.
// x: [64, 480000] f32, b: [16] f32, y: [64, 480000] f32.
//
// R12 ncu: nothing saturated (issue 62.5%, L1 60.5%, DRAM 57.5%) -> the
// shfl/select window assembly made the kernel issue/latency co-bound.
// This version halves the FMA stream with sm_103a packed fma.rn.f32x2
// (pairing the two 128-float sub-panels per accumulator/operand), and
// halves the shuffle stream by selecting prev/cur on each lane's OWN
// registers before a single 64-bit rotation (merge-before-rotate), while
// keeping the exact-once coalesced load scheme with register-chained halo.
// ~150 warp-instr per 256 outputs (was ~230); DRAM becomes the binder.

#define T_LEN    480000
#define NTAPS    16
#define BATCH    64
#define TILE     256                       // floats per warp tile (2 sub-panels)
#define N_TILES  (T_LEN / TILE)            // 1875 tiles per row
#define T_PER    5                         // tiles per warp chain
#define N_CHAIN  (N_TILES / T_PER)         // 375 chains per row
#define WARPS_PB 8
#define BLOCK    (WARPS_PB * 32)

typedef unsigned long long u64;

__device__ __forceinline__ u64 pack2(float lo, float hi) {
    u64 r; asm("mov.b64 %0, {%1, %2};" : "=l"(r) : "f"(lo), "f"(hi)); return r;
}
__device__ __forceinline__ void unpack2(u64 v, float& lo, float& hi) {
    asm("mov.b64 {%0, %1}, %2;" : "=f"(lo), "=f"(hi) : "l"(v));
}
// acc += a * b, two independent fp32 FMAs in one SASS FFMA2
__device__ __forceinline__ void fma2(u64& acc, u64 a, u64 b) {
    asm("fma.rn.f32x2 %0, %1, %2, %0;" : "+l"(acc) : "l"(a), "l"(b));
}
__device__ __forceinline__ u64 shfl64(u64 v, int src) {
    return __shfl_sync(0xffffffffu, v, src);
}

__global__ __launch_bounds__(BLOCK, 3)
void fir_apply_kernel(const float* __restrict__ x,
                      const float* __restrict__ b,
                      float* __restrict__ y)
{
    const int lane  = threadIdx.x & 31;
    const int warp  = threadIdx.x >> 5;
    const int chain = blockIdx.x * WARPS_PB + warp;
    if (chain >= N_CHAIN) return;            // warp-uniform exit
    const int row = blockIdx.y;

    const float4* __restrict__ x4 = reinterpret_cast<const float4*>(x + (size_t)row * T_LEN);
    float4* __restrict__ y4 = reinterpret_cast<float4*>(y + (size_t)row * T_LEN);

    // ---- taps, packed (b[k], b[k]) — amortized over the 5-tile chain ----
    u64 bbp[NTAPS];
    {
        const float4* b4 = reinterpret_cast<const float4*>(b);
        float4 q0 = __ldg(b4 + 0), q1 = __ldg(b4 + 1),
               q2 = __ldg(b4 + 2), q3 = __ldg(b4 + 3);
        bbp[0]  = pack2(q0.x, q0.x); bbp[1]  = pack2(q0.y, q0.y);
        bbp[2]  = pack2(q0.z, q0.z); bbp[3]  = pack2(q0.w, q0.w);
        bbp[4]  = pack2(q1.x, q1.x); bbp[5]  = pack2(q1.y, q1.y);
        bbp[6]  = pack2(q1.z, q1.z); bbp[7]  = pack2(q1.w, q1.w);
        bbp[8]  = pack2(q2.x, q2.x); bbp[9]  = pack2(q2.y, q2.y);
        bbp[10] = pack2(q2.z, q2.z); bbp[11] = pack2(q2.w, q2.w);
        bbp[12] = pack2(q3.x, q3.x); bbp[13] = pack2(q3.y, q3.y);
        bbp[14] = pack2(q3.z, q3.z); bbp[15] = pack2(q3.w, q3.w);
    }

    int pb4 = chain * T_PER * (TILE / 4);    // float4 index of tile base

    // halo: lanes 28..31 hold x[pb-16+4(lane-28) .. +3]; chain 0 -> zeros
    float4 hv = make_float4(0.f, 0.f, 0.f, 0.f);
    if (chain > 0 && lane >= 28)
        hv = __ldg(x4 + (pb4 - 4 + (lane - 28)));

    float4 v0 = __ldg(x4 + pb4 + lane);          // sub-panel 0: x[t0..t0+3]
    float4 v1 = __ldg(x4 + pb4 + 32 + lane);     // sub-panel 1: x[t0+128..]

    // merge predicates (lane-invariant across the chain)
    const bool p28 = (lane >= 28);   // d = 4
    const bool p29 = (lane >= 29);   // d = 3
    const bool p30 = (lane >= 30);   // d = 2
    const bool p31 = (lane >= 31);   // d = 1

    #pragma unroll 1
    for (int t = 0; t < T_PER; t++) {
        // prefetch next tile (overlap DRAM latency with compute)
        float4 nv0 = make_float4(0.f, 0.f, 0.f, 0.f);
        float4 nv1 = make_float4(0.f, 0.f, 0.f, 0.f);
        if (t < T_PER - 1) {
            nv0 = __ldg(x4 + pb4 + 64 + lane);
            nv1 = __ldg(x4 + pb4 + 96 + lane);
        }

        // pair registers: pv = (halo_panel0, halo_panel1) source = (hv, v0)
        //                 cv = (cur_panel0,  cur_panel1)  source = (v0, v1)
        u64 pv[4], cv[4];
        pv[0] = pack2(hv.x, v0.x); cv[0] = pack2(v0.x, v1.x);
        pv[1] = pack2(hv.y, v0.y); cv[1] = pack2(v0.y, v1.y);
        pv[2] = pack2(hv.z, v0.z); cv[2] = pack2(v0.z, v1.z);
        pv[3] = pack2(hv.w, v0.w); cv[3] = pack2(v0.w, v1.w);

        u64 acc[4];
        acc[0] = 0ull; acc[1] = 0ull; acc[2] = 0ull; acc[3] = 0ull;

        // window pair wp[m] = (x[t0-16+m], x[t0+112+m]); consumed per-d.
        // acc[jo] += bbp[k] * wp[16+jo-k]  <=>  wp[m] feeds k = 16+jo-m.

        // ---- d = 4: wp[1..3]  (wp[0] would need tap k=16 -> skipped) ----
        {
            const int src = (lane - 4) & 31;
            u64 w1 = shfl64(p28 ? pv[1] : cv[1], src);
            u64 w2 = shfl64(p28 ? pv[2] : cv[2], src);
            u64 w3 = shfl64(p28 ? pv[3] : cv[3], src);
            fma2(acc[0], bbp[15], w1);
            fma2(acc[0], bbp[14], w2); fma2(acc[1], bbp[15], w2);
            fma2(acc[0], bbp[13], w3); fma2(acc[1], bbp[14], w3);
            fma2(acc[2], bbp[15], w3);
        }
        // ---- d = 3: wp[4+j], k = 12 + jo - j ----
        {
            const int src = (lane - 3) & 31;
            #pragma unroll
            for (int j = 0; j < 4; j++) {
                u64 w = shfl64(p29 ? pv[j] : cv[j], src);
                #pragma unroll
                for (int jo = 0; jo < 4; jo++)
                    fma2(acc[jo], bbp[12 + jo - j], w);
            }
        }
        // ---- d = 2: wp[8+j], k = 8 + jo - j ----
        {
            const int src = (lane - 2) & 31;
            #pragma unroll
            for (int j = 0; j < 4; j++) {
                u64 w = shfl64(p30 ? pv[j] : cv[j], src);
                #pragma unroll
                for (int jo = 0; jo < 4; jo++)
                    fma2(acc[jo], bbp[8 + jo - j], w);
            }
        }
        // ---- d = 1: wp[12+j], k = 4 + jo - j ----
        {
            const int src = (lane - 1) & 31;
            #pragma unroll
            for (int j = 0; j < 4; j++) {
                u64 w = shfl64(p31 ? pv[j] : cv[j], src);
                #pragma unroll
                for (int jo = 0; jo < 4; jo++)
                    fma2(acc[jo], bbp[4 + jo - j], w);
            }
        }
        // ---- center: wp[16+j] = cv[j], k = jo - j (jo >= j) ----
        #pragma unroll
        for (int j = 0; j < 4; j++)
            #pragma unroll
            for (int jo = j; jo < 4; jo++)
                fma2(acc[jo], bbp[jo - j], cv[j]);

        // ---- unpack + coalesced stores (panel0, panel1) ----
        float l0, h0, l1, h1, l2, h2, l3, h3;
        unpack2(acc[0], l0, h0); unpack2(acc[1], l1, h1);
        unpack2(acc[2], l2, h2); unpack2(acc[3], l3, h3);
        y4[pb4 + lane]      = make_float4(l0, l1, l2, l3);
        y4[pb4 + 32 + lane] = make_float4(h0, h1, h2, h3);

        // slide the chain: next tile's halo = this tile's v1
        hv = v1;
        v0 = nv0;
        v1 = nv1;
        pb4 += 64;
    }
}

extern "C" void kernel_launch(void* const* d_in, const int* in_sizes, int n_in,
                              void* d_out, int out_size)
{
    const float* x = (const float*)d_in[0];   // [64, 480000] f32
    const float* b = (const float*)d_in[1];   // [16] f32
    float* y = (float*)d_out;                 // [64, 480000] f32

    dim3 grid((N_CHAIN + WARPS_PB - 1) / WARPS_PB, BATCH, 1);   // (47, 64)
    fir_apply_kernel<<<grid, BLOCK>>>(x, b, y);
}

// round 15
// speedup vs baseline: 1.5085x; 1.0905x over previous
#include <cuda_runtime.h>

// Causal FIR: y[r][t] = sum_{k=0}^{15} b[k] * x[r][t-k], zero init per row.
// x: [64, 480000] f32, b: [16] f32, y: [64, 480000] f32.
//
// R14 ncu: issue 47.5, L1 50, DRAM 61.6, occ 31.6 — latency-bound: at 72
// regs a 256-thread block quantizes to 3 blocks = 24 warps/SM, too few to
// hide shfl (26cyc) + DRAM latency. This round: 128-thread blocks (7 blocks
// = 28 warps/SM at the same 72 regs), first-use mul.rn.f32x2 instead of
// acc zero-init, and carried pointers instead of per-tile address rebuilds.
// Dataflow unchanged: exact-once coalesced LDG.128, register-chained halo
// across 5-tile warp chains, merged 64-bit shuffles, packed FFMA2.

#define T_LEN    480000
#define NTAPS    16
#define BATCH    64
#define TILE     256                       // floats per warp tile (2 sub-panels)
#define N_TILES  (T_LEN / TILE)            // 1875 tiles per row
#define T_PER    5                         // tiles per warp chain
#define N_CHAIN  (N_TILES / T_PER)         // 375 chains per row
#define WARPS_PB 4
#define BLOCK    (WARPS_PB * 32)           // 128 threads

typedef unsigned long long u64;

__device__ __forceinline__ u64 pack2(float lo, float hi) {
    u64 r; asm("mov.b64 %0, {%1, %2};" : "=l"(r) : "f"(lo), "f"(hi)); return r;
}
__device__ __forceinline__ void unpack2(u64 v, float& lo, float& hi) {
    asm("mov.b64 {%0, %1}, %2;" : "=f"(lo), "=f"(hi) : "l"(v));
}
// acc += a * b : two independent fp32 FMAs in one SASS FFMA2
__device__ __forceinline__ void fma2(u64& acc, u64 a, u64 b) {
    asm("fma.rn.f32x2 %0, %1, %2, %0;" : "+l"(acc) : "l"(a), "l"(b));
}
// r = a * b : packed multiply (first use of each accumulator)
__device__ __forceinline__ u64 mul2(u64 a, u64 b) {
    u64 r; asm("mul.rn.f32x2 %0, %1, %2;" : "=l"(r) : "l"(a), "l"(b)); return r;
}
__device__ __forceinline__ u64 shfl64(u64 v, int src) {
    return __shfl_sync(0xffffffffu, v, src);
}

__global__ __launch_bounds__(BLOCK, 7)
void fir_apply_kernel(const float* __restrict__ x,
                      const float* __restrict__ b,
                      float* __restrict__ y)
{
    const int lane  = threadIdx.x & 31;
    const int warp  = threadIdx.x >> 5;
    const int chain = blockIdx.x * WARPS_PB + warp;
    if (chain >= N_CHAIN) return;            // warp-uniform exit
    const int row = blockIdx.y;

    const float4* __restrict__ x4 = reinterpret_cast<const float4*>(x + (size_t)row * T_LEN);
    float4* __restrict__ y4 = reinterpret_cast<float4*>(y + (size_t)row * T_LEN);

    // ---- taps, packed (b[k], b[k]) — amortized over the 5-tile chain ----
    u64 bbp[NTAPS];
    {
        const float4* b4 = reinterpret_cast<const float4*>(b);
        float4 q0 = __ldg(b4 + 0), q1 = __ldg(b4 + 1),
               q2 = __ldg(b4 + 2), q3 = __ldg(b4 + 3);
        bbp[0]  = pack2(q0.x, q0.x); bbp[1]  = pack2(q0.y, q0.y);
        bbp[2]  = pack2(q0.z, q0.z); bbp[3]  = pack2(q0.w, q0.w);
        bbp[4]  = pack2(q1.x, q1.x); bbp[5]  = pack2(q1.y, q1.y);
        bbp[6]  = pack2(q1.z, q1.z); bbp[7]  = pack2(q1.w, q1.w);
        bbp[8]  = pack2(q2.x, q2.x); bbp[9]  = pack2(q2.y, q2.y);
        bbp[10] = pack2(q2.z, q2.z); bbp[11] = pack2(q2.w, q2.w);
        bbp[12] = pack2(q3.x, q3.x); bbp[13] = pack2(q3.y, q3.y);
        bbp[14] = pack2(q3.z, q3.z); bbp[15] = pack2(q3.w, q3.w);
    }

    const int pb4 = chain * T_PER * (TILE / 4);   // float4 index of chain base

    // halo: lanes 28..31 hold x[pb-16+4(lane-28) .. +3]; chain 0 -> zeros
    float4 hv = make_float4(0.f, 0.f, 0.f, 0.f);
    if (chain > 0 && lane >= 28)
        hv = __ldg(x4 + (pb4 - 4 + (lane - 28)));

    // carried pointers (one 64-bit add each per tile)
    const float4* __restrict__ xp = x4 + pb4 + lane;
    float4* __restrict__ yp = y4 + pb4 + lane;

    float4 v0 = __ldg(xp);           // sub-panel 0: x[t0..t0+3]
    float4 v1 = __ldg(xp + 32);      // sub-panel 1: x[t0+128..t0+131]

    // merge predicates (lane-invariant across the chain)
    const bool p28 = (lane >= 28);   // d = 4
    const bool p29 = (lane >= 29);   // d = 3
    const bool p30 = (lane >= 30);   // d = 2
    const bool p31 = (lane >= 31);   // d = 1

    #pragma unroll 1
    for (int t = 0; t < T_PER; t++) {
        // prefetch next tile (overlap DRAM latency with compute)
        float4 nv0 = make_float4(0.f, 0.f, 0.f, 0.f);
        float4 nv1 = make_float4(0.f, 0.f, 0.f, 0.f);
        if (t < T_PER - 1) {
            nv0 = __ldg(xp + 64);
            nv1 = __ldg(xp + 96);
        }

        // pair registers: pv = (halo_p0, halo_p1) = (hv, v0)
        //                 cv = (cur_p0,  cur_p1)  = (v0, v1)
        u64 pv[4], cv[4];
        pv[0] = pack2(hv.x, v0.x); cv[0] = pack2(v0.x, v1.x);
        pv[1] = pack2(hv.y, v0.y); cv[1] = pack2(v0.y, v1.y);
        pv[2] = pack2(hv.z, v0.z); cv[2] = pack2(v0.z, v1.z);
        pv[3] = pack2(hv.w, v0.w); cv[3] = pack2(v0.w, v1.w);

        u64 a0, a1, a2, a3;

        // window pair wp[m] = (x[t0-16+m], x[t0+112+m]).
        // acc[jo] += bbp[k] * wp[16+jo-k]  <=>  wp[m] feeds k = 16+jo-m.

        // ---- d = 4: wp[1..3]  (wp[0] would need tap k=16 -> skipped) ----
        {
            const int src = (lane - 4) & 31;
            u64 w1 = shfl64(p28 ? pv[1] : cv[1], src);
            u64 w2 = shfl64(p28 ? pv[2] : cv[2], src);
            u64 w3 = shfl64(p28 ? pv[3] : cv[3], src);
            a0 = mul2(bbp[15], w1);
            fma2(a0, bbp[14], w2); a1 = mul2(bbp[15], w2);
            fma2(a0, bbp[13], w3); fma2(a1, bbp[14], w3);
            a2 = mul2(bbp[15], w3);
        }
        // ---- d = 3: wp[4+j], k = 12 + jo - j ----
        {
            const int src = (lane - 3) & 31;
            {   // j = 0: first use of a3
                u64 w = shfl64(p29 ? pv[0] : cv[0], src);
                fma2(a0, bbp[12], w); fma2(a1, bbp[13], w);
                fma2(a2, bbp[14], w); a3 = mul2(bbp[15], w);
            }
            #pragma unroll
            for (int j = 1; j < 4; j++) {
                u64 w = shfl64(p29 ? pv[j] : cv[j], src);
                fma2(a0, bbp[12 - j], w); fma2(a1, bbp[13 - j], w);
                fma2(a2, bbp[14 - j], w); fma2(a3, bbp[15 - j], w);
            }
        }
        // ---- d = 2: wp[8+j], k = 8 + jo - j ----
        {
            const int src = (lane - 2) & 31;
            #pragma unroll
            for (int j = 0; j < 4; j++) {
                u64 w = shfl64(p30 ? pv[j] : cv[j], src);
                fma2(a0, bbp[8 - j], w);  fma2(a1, bbp[9 - j], w);
                fma2(a2, bbp[10 - j], w); fma2(a3, bbp[11 - j], w);
            }
        }
        // ---- d = 1: wp[12+j], k = 4 + jo - j ----
        {
            const int src = (lane - 1) & 31;
            #pragma unroll
            for (int j = 0; j < 4; j++) {
                u64 w = shfl64(p31 ? pv[j] : cv[j], src);
                fma2(a0, bbp[4 - j], w); fma2(a1, bbp[5 - j], w);
                fma2(a2, bbp[6 - j], w); fma2(a3, bbp[7 - j], w);
            }
        }
        // ---- center: wp[16+j] = cv[j], k = jo - j (jo >= j) ----
        fma2(a0, bbp[0], cv[0]); fma2(a1, bbp[1], cv[0]);
        fma2(a2, bbp[2], cv[0]); fma2(a3, bbp[3], cv[0]);
        fma2(a1, bbp[0], cv[1]); fma2(a2, bbp[1], cv[1]);
        fma2(a3, bbp[2], cv[1]);
        fma2(a2, bbp[0], cv[2]); fma2(a3, bbp[1], cv[2]);
        fma2(a3, bbp[0], cv[3]);

        // ---- unpack + coalesced stores (panel0, panel1) ----
        float l0, h0, l1, h1, l2, h2, l3, h3;
        unpack2(a0, l0, h0); unpack2(a1, l1, h1);
        unpack2(a2, l2, h2); unpack2(a3, l3, h3);
        yp[0]  = make_float4(l0, l1, l2, l3);
        yp[32] = make_float4(h0, h1, h2, h3);

        // slide the chain: next tile's halo = this tile's v1
        hv = v1;
        v0 = nv0;
        v1 = nv1;
        xp += 64;
        yp += 64;
    }
}

extern "C" void kernel_launch(void* const* d_in, const int* in_sizes, int n_in,
                              void* d_out, int out_size)
{
    const float* x = (const float*)d_in[0];   // [64, 480000] f32
    const float* b = (const float*)d_in[1];   // [16] f32
    float* y = (float*)d_out;                 // [64, 480000] f32

    dim3 grid((N_CHAIN + WARPS_PB - 1) / WARPS_PB, BATCH, 1);   // (94, 64)
    fir_apply_kernel<<<grid, BLOCK>>>(x, b, y);
}